// round 1
// baseline (speedup 1.0000x reference)
#include <cuda_runtime.h>
#include <math.h>

#define BB 4
#define SS 512
#define JJ 24
#define HH 128
#define NHEAD 8
#define HSZ 16

// Scratch (device globals — no allocation allowed)
__device__ float g_q[BB*NHEAD*JJ*SS*HSZ];   // (b,n,j,s,d)
__device__ float g_k[BB*NHEAD*JJ*SS*HSZ];
__device__ float g_v[BB*NHEAD*JJ*SS*HSZ];
__device__ float g_ao[BB*SS*JJ*HH];         // attention out, (b,s,j,h) h=n*16+d

// ---------------------------------------------------------------------------
// Kernel 1: QKV projection.  For each (j,b,mat): X(512x128) @ W(128x128)
// W[h][n*16+d] = mat[n][j][h][d]
// grid (24, 4, 3), block 256, smem = (128*128 + 32*128)*4 = 80KB
// ---------------------------------------------------------------------------
__global__ void qkv_kernel(const float* __restrict__ x,
                           const float* __restrict__ qm,
                           const float* __restrict__ km,
                           const float* __restrict__ vm) {
    const int j = blockIdx.x;
    const int b = blockIdx.y;
    const int m = blockIdx.z;
    const float* W = (m == 0) ? qm : ((m == 1) ? km : vm);
    float* dst = (m == 0) ? g_q : ((m == 1) ? g_k : g_v);

    extern __shared__ float sm1[];
    float* sW = sm1;            // [128][128]  sW[h*128 + nd]
    float* sX = sm1 + HH * HH;  // [32][128]

    const int tid = threadIdx.x;

    // Load weights for this joint into SMEM
    for (int idx = tid; idx < HH * HH; idx += 256) {
        int h  = idx >> 7;
        int nd = idx & 127;
        int n  = nd >> 4;
        int d  = nd & 15;
        sW[idx] = W[((n * JJ + j) * HH + h) * HSZ + d];
    }

    const int col  = tid & 127;   // output column n*16+d
    const int half = tid >> 7;    // 0/1: row parity
    const int n = col >> 4, d = col & 15;
    float* drow = dst + (size_t)(((b * NHEAD + n) * JJ + j) * SS) * HSZ + d;

    const int CH = 32;
    for (int s0 = 0; s0 < SS; s0 += CH) {
        __syncthreads();  // protect sX reuse (and sW on first iter)
        for (int idx = tid * 4; idx < CH * HH; idx += 256 * 4) {
            int r = idx >> 7;
            int h = idx & 127;
            *(float4*)&sX[idx] =
                *(const float4*)&x[(size_t)((b * SS + s0 + r) * JJ + j) * HH + h];
        }
        __syncthreads();

        float acc[CH / 2];
        #pragma unroll
        for (int i = 0; i < CH / 2; i++) acc[i] = 0.f;

        for (int h = 0; h < HH; h += 4) {
            float w0 = sW[(h + 0) * HH + col];
            float w1 = sW[(h + 1) * HH + col];
            float w2 = sW[(h + 2) * HH + col];
            float w3 = sW[(h + 3) * HH + col];
            #pragma unroll
            for (int i = 0; i < CH / 2; i++) {
                const float4 xv = *(const float4*)&sX[(2 * i + half) * HH + h];
                acc[i] += xv.x * w0;
                acc[i] += xv.y * w1;
                acc[i] += xv.z * w2;
                acc[i] += xv.w * w3;
            }
        }
        #pragma unroll
        for (int i = 0; i < CH / 2; i++) {
            drow[(size_t)(s0 + 2 * i + half) * HSZ] = acc[i];
        }
    }
}

// ---------------------------------------------------------------------------
// Kernel 2: fused causal attention per (b,n,j). One thread per query s,
// online softmax, K/V tiles in SMEM.
// grid (24, 8, 4), block 512, smem = 512*16*2*4 = 64KB
// ---------------------------------------------------------------------------
__global__ void attn_kernel() {
    const int j = blockIdx.x;
    const int n = blockIdx.y;
    const int b = blockIdx.z;

    extern __shared__ float sm2[];
    float* sK = sm2;             // [512][16]
    float* sV = sm2 + SS * HSZ;  // [512][16]

    const int tid = threadIdx.x;  // 512
    const size_t base = (size_t)(((b * NHEAD + n) * JJ + j) * SS) * HSZ;

    for (int idx = tid * 4; idx < SS * HSZ; idx += 512 * 4) {
        *(float4*)&sK[idx] = *(const float4*)&g_k[base + idx];
        *(float4*)&sV[idx] = *(const float4*)&g_v[base + idx];
    }
    __syncthreads();

    const int s = tid;
    const float4 q0 = *(const float4*)&g_q[base + s * HSZ + 0];
    const float4 q1 = *(const float4*)&g_q[base + s * HSZ + 4];
    const float4 q2 = *(const float4*)&g_q[base + s * HSZ + 8];
    const float4 q3 = *(const float4*)&g_q[base + s * HSZ + 12];

    float m = -1e30f, l = 0.f;
    float acc[16];
    #pragma unroll
    for (int i = 0; i < 16; i++) acc[i] = 0.f;

    for (int t = 0; t <= s; ++t) {
        const float4 k0 = *(const float4*)&sK[t * HSZ + 0];
        const float4 k1 = *(const float4*)&sK[t * HSZ + 4];
        const float4 k2 = *(const float4*)&sK[t * HSZ + 8];
        const float4 k3 = *(const float4*)&sK[t * HSZ + 12];
        float d0 = q0.x * k0.x + q0.y * k0.y + q0.z * k0.z + q0.w * k0.w;
        float d1 = q1.x * k1.x + q1.y * k1.y + q1.z * k1.z + q1.w * k1.w;
        float d2 = q2.x * k2.x + q2.y * k2.y + q2.z * k2.z + q2.w * k2.w;
        float d3 = q3.x * k3.x + q3.y * k3.y + q3.z * k3.z + q3.w * k3.w;
        const float score = ((d0 + d1) + (d2 + d3)) * 0.25f;  // 1/sqrt(16)

        float p;
        if (score > m) {
            const float corr = __expf(m - score);
            m = score;
            #pragma unroll
            for (int i = 0; i < 16; i++) acc[i] *= corr;
            l = l * corr + 1.f;
            p = 1.f;
        } else {
            p = __expf(score - m);
            l += p;
        }

        const float4 v0 = *(const float4*)&sV[t * HSZ + 0];
        const float4 v1 = *(const float4*)&sV[t * HSZ + 4];
        const float4 v2 = *(const float4*)&sV[t * HSZ + 8];
        const float4 v3 = *(const float4*)&sV[t * HSZ + 12];
        acc[0]  += p * v0.x;  acc[1]  += p * v0.y;  acc[2]  += p * v0.z;  acc[3]  += p * v0.w;
        acc[4]  += p * v1.x;  acc[5]  += p * v1.y;  acc[6]  += p * v1.z;  acc[7]  += p * v1.w;
        acc[8]  += p * v2.x;  acc[9]  += p * v2.y;  acc[10] += p * v2.z;  acc[11] += p * v2.w;
        acc[12] += p * v3.x;  acc[13] += p * v3.y;  acc[14] += p * v3.z;  acc[15] += p * v3.w;
    }

    const float inv = 1.f / l;
    float* o = &g_ao[(size_t)((b * SS + s) * JJ + j) * HH + n * HSZ];
    #pragma unroll
    for (int i = 0; i < 4; i++) {
        float4 r;
        r.x = acc[4 * i + 0] * inv;
        r.y = acc[4 * i + 1] * inv;
        r.z = acc[4 * i + 2] * inv;
        r.w = acc[4 * i + 3] * inv;
        *(float4*)&o[4 * i] = r;
    }
}

// ---------------------------------------------------------------------------
// Kernel 3: per-joint output projection.  y[r][k] = sum_h ao[r][h]*P[j][h][k]
// grid (24, 16), block 256, smem = (128*128 + 32*128)*4 = 80KB
// ---------------------------------------------------------------------------
__global__ void proj_kernel(const float* __restrict__ P, float* __restrict__ out) {
    const int j  = blockIdx.x;
    const int r0 = blockIdx.y * 128;  // row index over (b*S+s)

    extern __shared__ float sm3[];
    float* sP = sm3;            // [128][128]
    float* sA = sm3 + HH * HH;  // [32][128]

    const int tid = threadIdx.x;

    for (int idx = tid * 4; idx < HH * HH; idx += 256 * 4) {
        *(float4*)&sP[idx] = *(const float4*)&P[(size_t)j * HH * HH + idx];
    }

    const int col  = tid & 127;
    const int half = tid >> 7;

    for (int c = 0; c < 128; c += 32) {
        __syncthreads();
        for (int idx = tid * 4; idx < 32 * HH; idx += 256 * 4) {
            int r = idx >> 7;
            int h = idx & 127;
            *(float4*)&sA[idx] =
                *(const float4*)&g_ao[(size_t)((r0 + c + r) * JJ + j) * HH + h];
        }
        __syncthreads();

        float acc[16];
        #pragma unroll
        for (int i = 0; i < 16; i++) acc[i] = 0.f;

        for (int h = 0; h < HH; h += 4) {
            float w0 = sP[(h + 0) * HH + col];
            float w1 = sP[(h + 1) * HH + col];
            float w2 = sP[(h + 2) * HH + col];
            float w3 = sP[(h + 3) * HH + col];
            #pragma unroll
            for (int i = 0; i < 16; i++) {
                const float4 a = *(const float4*)&sA[(2 * i + half) * HH + h];
                acc[i] += a.x * w0;
                acc[i] += a.y * w1;
                acc[i] += a.z * w2;
                acc[i] += a.w * w3;
            }
        }
        #pragma unroll
        for (int i = 0; i < 16; i++) {
            out[(size_t)((r0 + c + 2 * i + half) * JJ + j) * HH + col] = acc[i];
        }
    }
}

// ---------------------------------------------------------------------------
// Kernel 4: residual + LayerNorm, in place on d_out. One warp per row.
// ---------------------------------------------------------------------------
__global__ void ln_kernel(const float* __restrict__ x,
                          const float* __restrict__ gamma,
                          const float* __restrict__ beta,
                          float* __restrict__ out) {
    const int row  = blockIdx.x * 8 + (threadIdx.x >> 5);
    const int lane = threadIdx.x & 31;
    const size_t off = (size_t)row * HH + lane * 4;

    const float4 o  = *(const float4*)(out + off);
    const float4 xr = *(const float4*)(x + off);
    const float v0 = o.x + xr.x, v1 = o.y + xr.y, v2 = o.z + xr.z, v3 = o.w + xr.w;

    float sum = v0 + v1 + v2 + v3;
    float sq  = v0 * v0 + v1 * v1 + v2 * v2 + v3 * v3;
    #pragma unroll
    for (int d = 16; d; d >>= 1) {
        sum += __shfl_xor_sync(0xFFFFFFFFu, sum, d);
        sq  += __shfl_xor_sync(0xFFFFFFFFu, sq, d);
    }
    const float mu  = sum * (1.f / 128.f);
    const float var = sq * (1.f / 128.f) - mu * mu;
    const float rs  = rsqrtf(var + 1e-5f);

    const float4 g  = *(const float4*)(gamma + lane * 4);
    const float4 bt = *(const float4*)(beta + lane * 4);
    float4 r;
    r.x = (v0 - mu) * rs * g.x + bt.x;
    r.y = (v1 - mu) * rs * g.y + bt.y;
    r.z = (v2 - mu) * rs * g.z + bt.z;
    r.w = (v3 - mu) * rs * g.w + bt.w;
    *(float4*)(out + off) = r;
}

// ---------------------------------------------------------------------------
extern "C" void kernel_launch(void* const* d_in, const int* in_sizes, int n_in,
                              void* d_out, int out_size) {
    const float* x     = (const float*)d_in[0];
    // d_in[1] = mask: causal mask handled structurally (t <= s)
    const float* qm    = (const float*)d_in[2];
    const float* km    = (const float*)d_in[3];
    const float* vm    = (const float*)d_in[4];
    const float* pmat  = (const float*)d_in[5];
    const float* gamma = (const float*)d_in[6];
    const float* beta  = (const float*)d_in[7];
    float* out = (float*)d_out;

    const int smem_qkv  = (HH * HH + 32 * HH) * sizeof(float);  // 80KB
    const int smem_attn = SS * HSZ * 2 * sizeof(float);         // 64KB
    const int smem_proj = (HH * HH + 32 * HH) * sizeof(float);  // 80KB

    cudaFuncSetAttribute(qkv_kernel,  cudaFuncAttributeMaxDynamicSharedMemorySize, smem_qkv);
    cudaFuncSetAttribute(attn_kernel, cudaFuncAttributeMaxDynamicSharedMemorySize, smem_attn);
    cudaFuncSetAttribute(proj_kernel, cudaFuncAttributeMaxDynamicSharedMemorySize, smem_proj);

    dim3 g1(JJ, BB, 3);
    qkv_kernel<<<g1, 256, smem_qkv>>>(x, qm, km, vm);

    dim3 g2(JJ, NHEAD, BB);
    attn_kernel<<<g2, 512, smem_attn>>>();

    dim3 g3(JJ, (BB * SS) / 128);
    proj_kernel<<<g3, 256, smem_proj>>>(pmat, out);

    ln_kernel<<<(BB * SS * JJ) / 8, 256>>>(x, gamma, beta, out);
}